// round 4
// baseline (speedup 1.0000x reference)
#include <cuda_runtime.h>

#define NN 100000
#define EE 1600000

typedef unsigned long long ull;

// ---------------- device scratch ----------------
__device__ float g_x[NN * 128];
__device__ float g_h[NN * 128];
__device__ float g_z[NN * 128];
__device__ float g_als[NN * 4];
__device__ float g_ald[NN * 4];
__device__ int   g_deg[NN];
__device__ int   g_ptr[NN + 1];
__device__ int   g_pos[NN];
__device__ int   g_csrc[EE + NN];
__device__ int   g_part[128];
__device__ int   g_partex[128];

__device__ __forceinline__ float lrelu(float v, float s) { return v > 0.f ? v : s * v; }

// ---- packed f32x2 helpers (Blackwell FFMA2 path, fp32-exact) ----
__device__ __forceinline__ void fma2(ull& d, ull a, ull b) {
    asm("fma.rn.f32x2 %0, %1, %2, %0;" : "+l"(d) : "l"(a), "l"(b));
}
__device__ __forceinline__ ull dup2(float x) {
    ull r; asm("mov.b64 %0, {%1, %1};" : "=l"(r) : "f"(x)); return r;
}
__device__ __forceinline__ void unpack2(ull v, float& lo, float& hi) {
    asm("mov.b64 {%0, %1}, %2;" : "=f"(lo), "=f"(hi) : "l"(v));
}
__device__ __forceinline__ void ld2(const float* p, ull& x, ull& y) {
    ulonglong2 v = *(const ulonglong2*)p; x = v.x; y = v.y;   // one LDS.128
}

// ---------------- CSR build (dst-major), shared by both GAT layers ----------------
__global__ void k_init_deg() {
    int i = blockIdx.x * blockDim.x + threadIdx.x;
    if (i < NN) g_deg[i] = 1;  // self loop
}

__global__ void k_count(const int* __restrict__ ei) {
    int e = blockIdx.x * blockDim.x + threadIdx.x;
    if (e < EE) atomicAdd(&g_deg[ei[EE + e]], 1);
}

__global__ void k_scan1() {
    __shared__ int sm[1024];
    int t = threadIdx.x;
    int i = blockIdx.x * 1024 + t;
    int v = (i < NN) ? g_deg[i] : 0;
    sm[t] = v; __syncthreads();
    for (int off = 1; off < 1024; off <<= 1) {
        int x = (t >= off) ? sm[t - off] : 0;
        __syncthreads();
        sm[t] += x; __syncthreads();
    }
    if (i < NN) g_ptr[i + 1] = sm[t];
    if (t == 1023) g_part[blockIdx.x] = sm[t];
}

__global__ void k_scan2() {
    __shared__ int sm[128];
    int t = threadIdx.x;
    int v = (t < 98) ? g_part[t] : 0;
    sm[t] = v; __syncthreads();
    for (int off = 1; off < 128; off <<= 1) {
        int x = (t >= off) ? sm[t - off] : 0;
        __syncthreads();
        sm[t] += x; __syncthreads();
    }
    if (t < 98) g_partex[t] = sm[t] - v;
}

__global__ void k_scan3() {
    int t = threadIdx.x;
    int i = blockIdx.x * 1024 + t;
    if (i < NN) {
        int val = g_ptr[i + 1] + g_partex[blockIdx.x];
        g_ptr[i + 1] = val;
        g_pos[i] = val - g_deg[i];
        if (i == 0) g_ptr[0] = 0;
    }
}

__global__ void k_fill(const int* __restrict__ ei) {
    int idx = blockIdx.x * blockDim.x + threadIdx.x;
    if (idx < EE + NN) {
        int s, d;
        if (idx < EE) { s = ei[idx]; d = ei[EE + idx]; }
        else          { s = idx - EE; d = s; }
        int p = atomicAdd(&g_pos[d], 1);
        g_csrc[p] = s;
    }
}

// ---------------- GEMM: A[n,128] @ B[128,128] (+bias, optional leaky) ----------------
// 256 thr, tile 256x128, thread tile 16x8, FFMA2 accumulators over row pairs.
// 0.75 B smem / MAC -> FFMA2-pipe-bound (LDS 192 cyc < FMA 256 cyc per k).
__global__ __launch_bounds__(256) void k_gemm128(
    const float* __restrict__ A, const float* __restrict__ B,
    const float* __restrict__ bias, float* __restrict__ C, int n, int doLeaky)
{
    __shared__ __align__(16) float As[32][260];
    __shared__ __align__(16) float Bs[32][132];
    int tid = threadIdx.x;
    int m0 = blockIdx.x * 256;
    int tr = tid >> 4, tc = tid & 15;   // 16 row-threads x 16 rows, 16 col-threads x 8 cols
    ull acc2[64];                        // [ci*8 + rp]
#pragma unroll
    for (int i = 0; i < 64; i++) acc2[i] = 0ull;

    for (int kc = 0; kc < 128; kc += 32) {
#pragma unroll
        for (int i = 0; i < 8; i++) {            // A tile 256x32 (store transposed)
            int idx = i * 256 + tid;
            int r = idx >> 3, kq = idx & 7;
            float4 f = make_float4(0.f, 0.f, 0.f, 0.f);
            if (m0 + r < n) f = *(const float4*)&A[(size_t)(m0 + r) * 128 + kc + kq * 4];
            As[kq * 4 + 0][r] = f.x; As[kq * 4 + 1][r] = f.y;
            As[kq * 4 + 2][r] = f.z; As[kq * 4 + 3][r] = f.w;
        }
#pragma unroll
        for (int i = 0; i < 4; i++) {            // B tile 32x128
            int idx = i * 256 + tid;
            int k = idx >> 5, cq = idx & 31;
            *(float4*)&Bs[k][cq * 4] = *(const float4*)&B[(kc + k) * 128 + cq * 4];
        }
        __syncthreads();
#pragma unroll
        for (int k = 0; k < 32; k++) {
            ull ap[8];
            ld2(&As[k][tr * 16 + 0],  ap[0], ap[1]);
            ld2(&As[k][tr * 16 + 4],  ap[2], ap[3]);
            ld2(&As[k][tr * 16 + 8],  ap[4], ap[5]);
            ld2(&As[k][tr * 16 + 12], ap[6], ap[7]);
            float4 b0 = *(const float4*)&Bs[k][tc * 4];
            float4 b1 = *(const float4*)&Bs[k][64 + tc * 4];
            ull bd[8];
            bd[0] = dup2(b0.x); bd[1] = dup2(b0.y); bd[2] = dup2(b0.z); bd[3] = dup2(b0.w);
            bd[4] = dup2(b1.x); bd[5] = dup2(b1.y); bd[6] = dup2(b1.z); bd[7] = dup2(b1.w);
#pragma unroll
            for (int ci = 0; ci < 8; ci++)
#pragma unroll
                for (int rp = 0; rp < 8; rp++)
                    fma2(acc2[ci * 8 + rp], ap[rp], bd[ci]);
        }
        __syncthreads();
    }

    float bb[8];
#pragma unroll
    for (int ci = 0; ci < 8; ci++) {
        int c = (ci < 4) ? tc * 4 + ci : 64 + tc * 4 + (ci - 4);
        bb[ci] = bias ? bias[c] : 0.f;
    }
#pragma unroll
    for (int rp = 0; rp < 8; rp++) {
        int rbase = tr * 16 + rp * 2;
#pragma unroll
        for (int half = 0; half < 2; half++) {
            int r = rbase + half;
            if (m0 + r < n) {
                float4 o0, o1;
                float lo, hi, v;
#pragma unroll
                for (int ci = 0; ci < 8; ci++) {
                    unpack2(acc2[ci * 8 + rp], lo, hi);
                    v = (half ? hi : lo) + bb[ci];
                    v = doLeaky ? lrelu(v, 0.01f) : v;
                    if (ci < 4) ((float*)&o0)[ci] = v; else ((float*)&o1)[ci - 4] = v;
                }
                *(float4*)&C[(size_t)(m0 + r) * 128 + tc * 4] = o0;
                *(float4*)&C[(size_t)(m0 + r) * 128 + 64 + tc * 4] = o1;
            }
        }
    }
}

// ---------------- GEMM: A[n,K] @ B[K,32] (+bias, leaky), C[:,colOff..+32) ----------------
// 128 thr, tile 256x32, thread tile 8x8, FFMA2. 1.0 B/MAC, multi-block/SM.
__global__ __launch_bounds__(128) void k_gemm_enc(
    const float* __restrict__ A, int lda,
    const float* __restrict__ B, const float* __restrict__ bias,
    float* __restrict__ C, int colOff, int n, int K)
{
    __shared__ __align__(16) float As[32][260];
    __shared__ __align__(16) float Bs[32][36];
    int tid = threadIdx.x;
    int m0 = blockIdx.x * 256;
    int tr = tid >> 2, tc = tid & 3;   // 32 row-threads x 8 rows, 4 col-threads x 8 cols
    ull acc2[32];                       // [ci*4 + rp]
#pragma unroll
    for (int i = 0; i < 32; i++) acc2[i] = 0ull;

    for (int kc = 0; kc < K; kc += 32) {
#pragma unroll
        for (int i = 0; i < 16; i++) {           // A tile 256x32 (store transposed)
            int idx = i * 128 + tid;
            int r = idx >> 3, kq = idx & 7;
            float4 f = make_float4(0.f, 0.f, 0.f, 0.f);
            if (m0 + r < n) f = *(const float4*)&A[(size_t)(m0 + r) * lda + kc + kq * 4];
            As[kq * 4 + 0][r] = f.x; As[kq * 4 + 1][r] = f.y;
            As[kq * 4 + 2][r] = f.z; As[kq * 4 + 3][r] = f.w;
        }
#pragma unroll
        for (int i = 0; i < 2; i++) {            // B tile 32x32
            int idx = i * 128 + tid;
            int k = idx >> 3, cq = idx & 7;
            *(float4*)&Bs[k][cq * 4] = *(const float4*)&B[(kc + k) * 32 + cq * 4];
        }
        __syncthreads();
#pragma unroll
        for (int k = 0; k < 32; k++) {
            ull ap[4];
            ld2(&As[k][tr * 8 + 0], ap[0], ap[1]);
            ld2(&As[k][tr * 8 + 4], ap[2], ap[3]);
            float4 b0 = *(const float4*)&Bs[k][tc * 8];
            float4 b1 = *(const float4*)&Bs[k][tc * 8 + 4];
            ull bd[8];
            bd[0] = dup2(b0.x); bd[1] = dup2(b0.y); bd[2] = dup2(b0.z); bd[3] = dup2(b0.w);
            bd[4] = dup2(b1.x); bd[5] = dup2(b1.y); bd[6] = dup2(b1.z); bd[7] = dup2(b1.w);
#pragma unroll
            for (int ci = 0; ci < 8; ci++)
#pragma unroll
                for (int rp = 0; rp < 4; rp++)
                    fma2(acc2[ci * 4 + rp], ap[rp], bd[ci]);
        }
        __syncthreads();
    }

    float bb[8];
#pragma unroll
    for (int ci = 0; ci < 8; ci++) bb[ci] = bias[tc * 8 + ci];
#pragma unroll
    for (int rp = 0; rp < 4; rp++) {
        int rbase = tr * 8 + rp * 2;
#pragma unroll
        for (int half = 0; half < 2; half++) {
            int r = rbase + half;
            if (m0 + r < n) {
                float4 o0, o1;
                float lo, hi, v;
#pragma unroll
                for (int ci = 0; ci < 8; ci++) {
                    unpack2(acc2[ci * 4 + rp], lo, hi);
                    v = lrelu((half ? hi : lo) + bb[ci], 0.01f);
                    if (ci < 4) ((float*)&o0)[ci] = v; else ((float*)&o1)[ci - 4] = v;
                }
                *(float4*)&C[(size_t)(m0 + r) * 128 + colOff + tc * 8] = o0;
                *(float4*)&C[(size_t)(m0 + r) * 128 + colOff + tc * 8 + 4] = o1;
            }
        }
    }
}

// ---------------- tiny encoders (num_prop 5->32, cat_prop 3->32) ----------------
__global__ void k_small(const float* __restrict__ np_, const float* __restrict__ cp,
                        const float* __restrict__ Wnp, const float* __restrict__ bnp,
                        const float* __restrict__ Wcp, const float* __restrict__ bcp)
{
    int g = blockIdx.x * blockDim.x + threadIdx.x;
    int nID = g >> 5, c = g & 31;
    if (nID >= NN) return;
    float s = bnp[c];
#pragma unroll
    for (int k = 0; k < 5; k++) s += __ldg(&np_[nID * 5 + k]) * Wnp[k * 32 + c];
    g_x[(size_t)nID * 128 + 64 + c] = lrelu(s, 0.01f);
    float s2 = bcp[c];
#pragma unroll
    for (int k = 0; k < 3; k++) s2 += __ldg(&cp[nID * 3 + k]) * Wcp[k * 32 + c];
    g_x[(size_t)nID * 128 + 96 + c] = lrelu(s2, 0.01f);
}

// ---------------- per-node attention logit halves: als/ald ----------------
__global__ void k_al(const float* __restrict__ h, const float* __restrict__ asrc,
                     const float* __restrict__ adst, int n, int H)
{
    int w = (blockIdx.x * blockDim.x + threadIdx.x) >> 5;
    int lane = threadIdx.x & 31;
    if (w >= n) return;
    float ps[4], pd[4];
#pragma unroll
    for (int q = 0; q < 4; q++) {
        float hv = h[(size_t)w * 128 + q * 32 + lane];
        ps[q] = hv * asrc[q * 32 + lane];
        pd[q] = hv * adst[q * 32 + lane];
    }
    if (H == 1) { ps[0] += ps[1] + ps[2] + ps[3]; pd[0] += pd[1] + pd[2] + pd[3]; }
    int QQ = (H == 4) ? 4 : 1;
    for (int q = 0; q < QQ; q++) {
        float s1 = ps[q], s2 = pd[q];
        for (int off = 16; off; off >>= 1) {
            s1 += __shfl_xor_sync(0xffffffffu, s1, off);
            s2 += __shfl_xor_sync(0xffffffffu, s2, off);
        }
        if (lane == 0) { g_als[(size_t)w * H + q] = s1; g_ald[(size_t)w * H + q] = s2; }
    }
}

// ---------------- GAT aggregation: warp per node, CSR gather, two-sweep softmax ----------------
__global__ void k_gat(const float* __restrict__ h, const float* __restrict__ bias,
                      float* __restrict__ out, int n, int H)
{
    int w = (blockIdx.x * blockDim.x + threadIdx.x) >> 5;
    int lane = threadIdx.x & 31;
    if (w >= n) return;
    int beg = g_ptr[w], end = g_ptr[w + 1];
    float aldv = (lane < H) ? g_ald[(size_t)w * H + lane] : 0.f;

    float mx = -1e30f;
    for (int e = beg; e < end; e++) {
        int src = __ldg(&g_csrc[e]);
        if (lane < H) {
            float v = g_als[(size_t)src * H + lane] + aldv;
            v = v > 0.f ? v : 0.2f * v;
            mx = fmaxf(mx, v);
        }
    }

    float s[4] = {0.f, 0.f, 0.f, 0.f}, acc[4] = {0.f, 0.f, 0.f, 0.f};
    for (int e = beg; e < end; e++) {
        int src = __ldg(&g_csrc[e]);
        float wv = 0.f;
        if (lane < H) {
            float v = g_als[(size_t)src * H + lane] + aldv;
            v = v > 0.f ? v : 0.2f * v;
            wv = __expf(v - mx);
        }
#pragma unroll
        for (int q = 0; q < 4; q++) {
            int hq = (H == 4) ? q : 0;
            float wq = __shfl_sync(0xffffffffu, wv, hq);
            float hv = __ldg(&h[(size_t)src * 128 + q * 32 + lane]);
            s[q] += wq;
            acc[q] += wq * hv;
        }
    }
#pragma unroll
    for (int q = 0; q < 4; q++) {
        int ch = q * 32 + lane;
        out[(size_t)w * 128 + ch] = acc[q] / (s[q] + 1e-16f) + bias[ch];
    }
}

// ---------------- output head: z[n,128] @ W_o2[128,2] + b ----------------
__global__ void k_out(const float* __restrict__ z, const float* __restrict__ W,
                      const float* __restrict__ b, float* __restrict__ out, int n)
{
    int w = (blockIdx.x * blockDim.x + threadIdx.x) >> 5;
    int lane = threadIdx.x & 31;
    if (w >= n) return;
    float p0 = 0.f, p1 = 0.f;
#pragma unroll
    for (int q = 0; q < 4; q++) {
        int ch = q * 32 + lane;
        float zv = z[(size_t)w * 128 + ch];
        p0 += zv * W[ch * 2];
        p1 += zv * W[ch * 2 + 1];
    }
    for (int off = 16; off; off >>= 1) {
        p0 += __shfl_xor_sync(0xffffffffu, p0, off);
        p1 += __shfl_xor_sync(0xffffffffu, p1, off);
    }
    if (lane == 0) { out[2 * w] = p0 + b[0]; out[2 * w + 1] = p1 + b[1]; }
}

// ---------------- launch ----------------
extern "C" void kernel_launch(void* const* d_in, const int* in_sizes, int n_in,
                              void* d_out, int out_size)
{
    const float* des  = (const float*)d_in[0];
    const float* tw   = (const float*)d_in[1];
    const float* np_  = (const float*)d_in[2];
    const float* cp   = (const float*)d_in[3];
    const int*   ei   = (const int*)d_in[4];
    const float* W_des = (const float*)d_in[5];  const float* b_des = (const float*)d_in[6];
    const float* W_tw  = (const float*)d_in[7];  const float* b_tw  = (const float*)d_in[8];
    const float* W_np  = (const float*)d_in[9];  const float* b_np  = (const float*)d_in[10];
    const float* W_cp  = (const float*)d_in[11]; const float* b_cp  = (const float*)d_in[12];
    const float* W_in  = (const float*)d_in[13]; const float* b_in  = (const float*)d_in[14];
    const float* g1W   = (const float*)d_in[15]; const float* g1as  = (const float*)d_in[16];
    const float* g1ad  = (const float*)d_in[17]; const float* g1b   = (const float*)d_in[18];
    const float* g2W   = (const float*)d_in[19]; const float* g2as  = (const float*)d_in[20];
    const float* g2ad  = (const float*)d_in[21]; const float* g2b   = (const float*)d_in[22];
    const float* Wo1   = (const float*)d_in[23]; const float* bo1   = (const float*)d_in[24];
    const float* Wo2   = (const float*)d_in[25]; const float* bo2   = (const float*)d_in[26];
    float* out = (float*)d_out;

    float *px, *ph, *pz;
    cudaGetSymbolAddress((void**)&px, g_x);
    cudaGetSymbolAddress((void**)&ph, g_h);
    cudaGetSymbolAddress((void**)&pz, g_z);

    // one-time side stream + events (created on the uncaptured correctness call)
    static cudaStream_t s2 = nullptr;
    static cudaEvent_t evFork = nullptr, evJoin = nullptr;
    if (!s2) {
        cudaStreamCreateWithFlags(&s2, cudaStreamNonBlocking);
        cudaEventCreateWithFlags(&evFork, cudaEventDisableTiming);
        cudaEventCreateWithFlags(&evJoin, cudaEventDisableTiming);
    }

    // fork point: CSR branch depends on nothing done this call
    cudaEventRecord(evFork, 0);

    const int G256 = (NN + 255) / 256;   // 391

    // feature encoding -> g_x [N,128]   (main stream)
    k_small<<<(NN * 32 + 255) / 256, 256>>>(np_, cp, W_np, b_np, W_cp, b_cp);   // launch 0
    k_gemm_enc<<<G256, 128>>>(des, 768, W_des, b_des, px, 0, NN, 768);          // 1
    k_gemm_enc<<<G256, 128>>>(tw,  768, W_tw,  b_tw,  px, 32, NN, 768);         // 2

    // input linear + gat1 transform + logits
    k_gemm128<<<G256, 256>>>(px, W_in, b_in, ph, NN, 1);                        // 3 (profiled slot)
    k_gemm128<<<G256, 256>>>(ph, g1W, nullptr, pz, NN, 0);                      // 4
    k_al<<<(NN + 7) / 8, 256>>>(pz, g1as, g1ad, NN, 4);                         // 5

    // CSR build on side stream, overlapping the GEMMs above
    cudaStreamWaitEvent(s2, evFork, 0);
    k_init_deg<<<(NN + 255) / 256, 256, 0, s2>>>();
    k_count<<<(EE + 255) / 256, 256, 0, s2>>>(ei);
    k_scan1<<<98, 1024, 0, s2>>>();
    k_scan2<<<1, 128, 0, s2>>>();
    k_scan3<<<98, 1024, 0, s2>>>();
    k_fill<<<(EE + NN + 255) / 256, 256, 0, s2>>>(ei);
    cudaEventRecord(evJoin, s2);
    cudaStreamWaitEvent(0, evJoin, 0);

    // GAT layer 1 aggregation (needs CSR)
    k_gat<<<(NN + 7) / 8, 256>>>(pz, g1b, px, NN, 4);

    // GAT layer 2 (H=1, C=128)
    k_gemm128<<<G256, 256>>>(px, g2W, nullptr, ph, NN, 0);
    k_al<<<(NN + 7) / 8, 256>>>(ph, g2as, g2ad, NN, 1);
    k_gat<<<(NN + 7) / 8, 256>>>(ph, g2b, pz, NN, 1);

    // output head
    k_gemm128<<<G256, 256>>>(pz, Wo1, bo1, px, NN, 1);
    k_out<<<(NN + 7) / 8, 256>>>(px, Wo2, bo2, out, NN);
}